// round 3
// baseline (speedup 1.0000x reference)
#include <cuda_runtime.h>
#include <cstdint>

#define NU 100000
#define NI 100000
#define D  128
#define EMAX 810000
#define NROWS 100000

typedef unsigned long long u64;

// ---------------- scratch ----------------------------------------------------
__device__ float g_acc_f [(size_t)NU * D];
__device__ float g_acc_rb[(size_t)NU * D];
__device__ float g_acc_r [(size_t)NI * D];
__device__ int   g_hist_f [NU];
__device__ int   g_hist_rb[NU];
__device__ int   g_hist_r [NI];
__device__ int   g_ptr_f [NU + 1];
__device__ int   g_ptr_rb[NU + 1];
__device__ int   g_ptr_r [NI + 1];
__device__ int   g_cur_f [NU];
__device__ int   g_cur_rb[NU];
__device__ int   g_cur_r [NI];
__device__ int   g_srcl_f [EMAX];
__device__ int   g_srcl_rb[EMAX];
__device__ int   g_srcl_r [EMAX];

// ---------------- zero histograms --------------------------------------------
__global__ void zero_hist_kernel() {
    int i = blockIdx.x * blockDim.x + threadIdx.x;
    if (i < NU) { g_hist_f[i] = 0; g_hist_rb[i] = 0; g_hist_r[i] = 0; }
}

// ---------------- fused histogram (3 etypes via gridDim.y) --------------------
__global__ __launch_bounds__(256) void hist3_kernel(
    const int* __restrict__ d0, const int* __restrict__ d1,
    const int* __restrict__ d2, int E0, int E1, int E2)
{
    int et = blockIdx.y;
    const int* dst = (et == 0) ? d0 : (et == 1) ? d1 : d2;
    int* hist = (et == 0) ? g_hist_f : (et == 1) ? g_hist_rb : g_hist_r;
    int E = (et == 0) ? E0 : (et == 1) ? E1 : E2;
    int i = blockIdx.x * blockDim.x + threadIdx.x;
    if (i < E) atomicAdd(&hist[dst[i]], 1);
}

// ---------------- per-etype exclusive scan (one block per etype) --------------
__global__ __launch_bounds__(1024) void scan_kernel(int n)
{
    const int* hist; int* ptr; int* cur;
    if      (blockIdx.x == 0) { hist = g_hist_f;  ptr = g_ptr_f;  cur = g_cur_f;  }
    else if (blockIdx.x == 1) { hist = g_hist_rb; ptr = g_ptr_rb; cur = g_cur_rb; }
    else                      { hist = g_hist_r;  ptr = g_ptr_r;  cur = g_cur_r;  }

    const int T = 1024;
    int chunk = (n + T - 1) / T;
    int lo = threadIdx.x * chunk;
    int hi = lo + chunk; if (hi > n) hi = n;
    if (lo > n) lo = n;

    int s = 0;
    for (int i = lo; i < hi; i++) s += hist[i];

    __shared__ int warpsum[32];
    int lane = threadIdx.x & 31, wid = threadIdx.x >> 5;
    int incl = s;
#pragma unroll
    for (int off = 1; off < 32; off <<= 1) {
        int t = __shfl_up_sync(0xffffffffu, incl, off);
        if (lane >= off) incl += t;
    }
    if (lane == 31) warpsum[wid] = incl;
    __syncthreads();
    if (wid == 0) {
        int w = warpsum[lane];
#pragma unroll
        for (int off = 1; off < 32; off <<= 1) {
            int t = __shfl_up_sync(0xffffffffu, w, off);
            if (lane >= off) w += t;
        }
        warpsum[lane] = w;
    }
    __syncthreads();
    int excl = incl - s + (wid ? warpsum[wid - 1] : 0);
    for (int i = lo; i < hi; i++) {
        ptr[i] = excl; cur[i] = excl; excl += hist[i];
    }
    if (threadIdx.x == 0) ptr[n] = warpsum[31];
}

// ---------------- fused permute -----------------------------------------------
__global__ __launch_bounds__(256) void permute3_kernel(
    const int* __restrict__ s0, const int* __restrict__ d0,
    const int* __restrict__ s1, const int* __restrict__ d1,
    const int* __restrict__ s2, const int* __restrict__ d2,
    int E0, int E1, int E2)
{
    int et = blockIdx.y;
    const int* src = (et == 0) ? s0 : (et == 1) ? s1 : s2;
    const int* dst = (et == 0) ? d0 : (et == 1) ? d1 : d2;
    int* cur = (et == 0) ? g_cur_f : (et == 1) ? g_cur_rb : g_cur_r;
    int* srclist = (et == 0) ? g_srcl_f : (et == 1) ? g_srcl_rb : g_srcl_r;
    int E = (et == 0) ? E0 : (et == 1) ? E1 : E2;
    int i = blockIdx.x * blockDim.x + threadIdx.x;
    if (i < E) {
        int d = dst[i];
        int p = atomicAdd(&cur[d], 1);
        srclist[p] = src[i];
    }
}

// ---------------- fused gather: one warp per node, deep unroll ----------------
__global__ __launch_bounds__(256) void gather3_kernel(
    const float4* __restrict__ feat_u, const float4* __restrict__ feat_i)
{
    int et = blockIdx.y;
    const float4* feat = (et == 1) ? feat_i : feat_u;
    const int* ptr = (et == 0) ? g_ptr_f : (et == 1) ? g_ptr_rb : g_ptr_r;
    const int* srclist = (et == 0) ? g_srcl_f : (et == 1) ? g_srcl_rb : g_srcl_r;
    float4* acc = (float4*)((et == 0) ? g_acc_f : (et == 1) ? g_acc_rb : g_acc_r);

    int node = (blockIdx.x * 256 + threadIdx.x) >> 5;
    int lane = threadIdx.x & 31;
    if (node >= NROWS) return;
    int beg = __ldg(&ptr[node]);
    int end = __ldg(&ptr[node + 1]);
    int deg = end - beg;

    float4 s = make_float4(0.f, 0.f, 0.f, 0.f);
    int e = beg;
    // burst of 8 independent row loads (mean degree = 8)
    for (; e + 8 <= end; e += 8) {
        int si[8];
#pragma unroll
        for (int j = 0; j < 8; j++) si[j] = __ldg(&srclist[e + j]);
        float4 v[8];
#pragma unroll
        for (int j = 0; j < 8; j++) v[j] = feat[(size_t)si[j] * 32 + lane];
#pragma unroll
        for (int j = 0; j < 8; j++) {
            s.x += v[j].x; s.y += v[j].y; s.z += v[j].z; s.w += v[j].w;
        }
    }
    for (; e + 4 <= end; e += 4) {
        int si[4];
#pragma unroll
        for (int j = 0; j < 4; j++) si[j] = __ldg(&srclist[e + j]);
        float4 v[4];
#pragma unroll
        for (int j = 0; j < 4; j++) v[j] = feat[(size_t)si[j] * 32 + lane];
#pragma unroll
        for (int j = 0; j < 4; j++) {
            s.x += v[j].x; s.y += v[j].y; s.z += v[j].z; s.w += v[j].w;
        }
    }
    for (; e < end; e++) {
        float4 v = feat[(size_t)__ldg(&srclist[e]) * 32 + lane];
        s.x += v.x; s.y += v.y; s.z += v.z; s.w += v.w;
    }
    float inv = __fdividef(1.0f, (float)(deg > 0 ? deg : 1));
    s.x *= inv; s.y *= inv; s.z *= inv; s.w *= inv;
    acc[(size_t)node * 32 + lane] = s;
}

// ---------------- packed fp32x2 helpers --------------------------------------
__device__ __forceinline__ u64 ffma2(u64 a, u64 b, u64 c) {
    u64 d;
    asm("fma.rn.f32x2 %0, %1, %2, %3;" : "=l"(d) : "l"(a), "l"(b), "l"(c));
    return d;
}
__device__ __forceinline__ u64 dup2(float x) {
    u64 r;
    asm("mov.b64 %0, {%1, %1};" : "=l"(r) : "f"(x));
    return r;
}
union F2U { u64 u; float2 f; };

// ---------------- fused GEMM --------------------------------------------------
// BM=256, BN=128, BK=32; 256 threads; thread tile 8 rows x 16 cols (8 u64).
// blockIdx.y==0: out_user = mean_f @ W_f^T + mean_rb @ W_rb^T + masked biases
// blockIdx.y==1: out_item = mean_r @ W_r^T + masked bias
__global__ __launch_bounds__(256, 1) void gemm_fused(
    float* __restrict__ out_user, float* __restrict__ out_item,
    const float* __restrict__ W_f, const float* __restrict__ b_f,
    const float* __restrict__ W_rb, const float* __restrict__ b_rb,
    const float* __restrict__ W_r, const float* __restrict__ b_r)
{
    __shared__ __align__(16) float As[32][256];
    __shared__ __align__(16) float Ws[32][128];

    const int tid = threadIdx.x;
    const int tx = tid & 7;          // 8 col groups x 16 cols
    const int ty = tid >> 3;         // 32 row groups x 8 rows
    const int row0 = blockIdx.x * 256;
    const bool user = (blockIdx.y == 0);
    const int nseg = user ? 2 : 1;
    float* out = user ? out_user : out_item;

    const int garow = row0 + tid;    // staged row for this thread
    const int w_n = tid & 127;
    const int w_h = (tid >> 7) * 16; // k-offset 0 or 16

    u64 C[8][8];
#pragma unroll
    for (int m = 0; m < 8; m++)
#pragma unroll
        for (int c = 0; c < 8; c++) C[m][c] = 0ull;

    for (int seg = 0; seg < nseg; seg++) {
        const float* acc = user ? (seg ? g_acc_rb : g_acc_f) : g_acc_r;
        const float* W = user ? (seg ? W_rb : W_f) : W_r;
        for (int kc = 0; kc < D; kc += 32) {
            // global loads (before sync, overlap with previous compute)
            float4 a[8];
            if (garow < NROWS) {
#pragma unroll
                for (int j = 0; j < 8; j++)
                    a[j] = *reinterpret_cast<const float4*>(
                        acc + (size_t)garow * D + kc + j * 4);
            } else {
#pragma unroll
                for (int j = 0; j < 8; j++)
                    a[j] = make_float4(0.f, 0.f, 0.f, 0.f);
            }
            float4 w[4];
#pragma unroll
            for (int j = 0; j < 4; j++)
                w[j] = *reinterpret_cast<const float4*>(
                    W + (size_t)w_n * D + kc + w_h + j * 4);

            __syncthreads();
#pragma unroll
            for (int j = 0; j < 8; j++) {
                As[j * 4 + 0][tid] = a[j].x;
                As[j * 4 + 1][tid] = a[j].y;
                As[j * 4 + 2][tid] = a[j].z;
                As[j * 4 + 3][tid] = a[j].w;
            }
#pragma unroll
            for (int j = 0; j < 4; j++) {
                Ws[w_h + j * 4 + 0][w_n] = w[j].x;
                Ws[w_h + j * 4 + 1][w_n] = w[j].y;
                Ws[w_h + j * 4 + 2][w_n] = w[j].z;
                Ws[w_h + j * 4 + 3][w_n] = w[j].w;
            }
            __syncthreads();

#pragma unroll 8
            for (int k = 0; k < 32; k++) {
                float4 a0 = *reinterpret_cast<const float4*>(&As[k][ty * 8]);
                float4 a1 = *reinterpret_cast<const float4*>(&As[k][ty * 8 + 4]);
                ulonglong2 w0 = *reinterpret_cast<const ulonglong2*>(&Ws[k][tx * 16]);
                ulonglong2 w1 = *reinterpret_cast<const ulonglong2*>(&Ws[k][tx * 16 + 4]);
                ulonglong2 w2 = *reinterpret_cast<const ulonglong2*>(&Ws[k][tx * 16 + 8]);
                ulonglong2 w3 = *reinterpret_cast<const ulonglong2*>(&Ws[k][tx * 16 + 12]);
                u64 ad[8];
                ad[0] = dup2(a0.x); ad[1] = dup2(a0.y);
                ad[2] = dup2(a0.z); ad[3] = dup2(a0.w);
                ad[4] = dup2(a1.x); ad[5] = dup2(a1.y);
                ad[6] = dup2(a1.z); ad[7] = dup2(a1.w);
                u64 wv[8];
                wv[0] = w0.x; wv[1] = w0.y; wv[2] = w1.x; wv[3] = w1.y;
                wv[4] = w2.x; wv[5] = w2.y; wv[6] = w3.x; wv[7] = w3.y;
#pragma unroll
                for (int m = 0; m < 8; m++)
#pragma unroll
                    for (int c = 0; c < 8; c++)
                        C[m][c] = ffma2(ad[m], wv[c], C[m][c]);
            }
        }
    }

    // epilogue: masked bias(es)
    const float* bias0 = user ? b_f : b_r;
    const int* cnt0 = user ? g_hist_f : g_hist_r;
    float4 bb0[4], bb1[4];
#pragma unroll
    for (int j = 0; j < 4; j++)
        bb0[j] = *reinterpret_cast<const float4*>(bias0 + tx * 16 + j * 4);
    if (user) {
#pragma unroll
        for (int j = 0; j < 4; j++)
            bb1[j] = *reinterpret_cast<const float4*>(b_rb + tx * 16 + j * 4);
    }
#pragma unroll
    for (int m = 0; m < 8; m++) {
        int r = row0 + ty * 8 + m;
        if (r >= NROWS) continue;
        float m0 = (cnt0[r] > 0) ? 1.0f : 0.0f;
        float m1 = (user && g_hist_rb[r] > 0) ? 1.0f : 0.0f;
#pragma unroll
        for (int j = 0; j < 4; j++) {
            F2U lo, hi;
            lo.u = C[m][2 * j]; hi.u = C[m][2 * j + 1];
            float4 o;
            o.x = lo.f.x + bb0[j].x * m0;
            o.y = lo.f.y + bb0[j].y * m0;
            o.z = hi.f.x + bb0[j].z * m0;
            o.w = hi.f.y + bb0[j].w * m0;
            if (user) {
                o.x += bb1[j].x * m1; o.y += bb1[j].y * m1;
                o.z += bb1[j].z * m1; o.w += bb1[j].w * m1;
            }
            *reinterpret_cast<float4*>(out + (size_t)r * D + tx * 16 + j * 4) = o;
        }
    }
}

// ---------------- launch ------------------------------------------------------
extern "C" void kernel_launch(void* const* d_in, const int* in_sizes, int n_in,
                              void* d_out, int out_size)
{
    const float* feat_user = (const float*)d_in[0];
    const float* feat_item = (const float*)d_in[1];
    const float* W_f  = (const float*)d_in[2];
    const float* b_f  = (const float*)d_in[3];
    const float* W_r  = (const float*)d_in[4];
    const float* b_r  = (const float*)d_in[5];
    const float* W_rb = (const float*)d_in[6];
    const float* b_rb = (const float*)d_in[7];
    const int* src_f  = (const int*)d_in[8];
    const int* dst_f  = (const int*)d_in[9];
    const int* src_r  = (const int*)d_in[10];
    const int* dst_r  = (const int*)d_in[11];
    const int* src_rb = (const int*)d_in[12];
    const int* dst_rb = (const int*)d_in[13];
    const int E_f  = in_sizes[8];
    const int E_rb = in_sizes[12];
    const int E_r  = in_sizes[10];

    float* out_user = (float*)d_out;
    float* out_item = (float*)d_out + (size_t)NU * D;

    int Emax = E_f > E_rb ? E_f : E_rb;
    if (E_r > Emax) Emax = E_r;

    // 1) zero histograms
    zero_hist_kernel<<<(NU + 255) / 256, 256>>>();

    // 2) histograms (etype order: 0=follows, 1=ratedby, 2=rates)
    {
        dim3 g((Emax + 255) / 256, 3);
        hist3_kernel<<<g, 256>>>(dst_f, dst_rb, dst_r, E_f, E_rb, E_r);
    }

    // 3) exclusive scans
    scan_kernel<<<3, 1024>>>(NU);

    // 4) build per-dst src lists
    {
        dim3 g((Emax + 255) / 256, 3);
        permute3_kernel<<<g, 256>>>(src_f, dst_f, src_rb, dst_rb, src_r, dst_r,
                                    E_f, E_rb, E_r);
    }

    // 5) gather means (one warp per node, 3 etypes)
    {
        dim3 g((NROWS * 32 + 255) / 256, 3);
        gather3_kernel<<<g, 256>>>((const float4*)feat_user,
                                   (const float4*)feat_item);
    }

    // 6) fused GEMMs
    {
        dim3 g((NROWS + 255) / 256, 2);
        gemm_fused<<<g, 256>>>(out_user, out_item,
                               W_f, b_f, W_rb, b_rb, W_r, b_r);
    }
}

// round 5
// speedup vs baseline: 1.3166x; 1.3166x over previous
#include <cuda_runtime.h>
#include <cstdint>

#define NU 100000
#define NI 100000
#define D  128
#define EMAX 810000
#define NROWS 100000

typedef unsigned long long u64;

// ---------------- scratch ----------------------------------------------------
__device__ float g_acc_f [(size_t)NU * D];
__device__ float g_acc_rb[(size_t)NU * D];
__device__ float g_acc_r [(size_t)NI * D];
__device__ int   g_hist_f [NU];
__device__ int   g_hist_rb[NU];
__device__ int   g_hist_r [NI];
__device__ int   g_ptr_f [NU + 1];
__device__ int   g_ptr_rb[NU + 1];
__device__ int   g_ptr_r [NI + 1];
__device__ int   g_cur_f [NU];
__device__ int   g_cur_rb[NU];
__device__ int   g_cur_r [NI];
__device__ int   g_srcl_f [EMAX];
__device__ int   g_srcl_rb[EMAX];
__device__ int   g_srcl_r [EMAX];

// ---------------- zero histograms --------------------------------------------
__global__ void zero_hist_kernel() {
    int i = blockIdx.x * blockDim.x + threadIdx.x;
    if (i < NU) { g_hist_f[i] = 0; g_hist_rb[i] = 0; g_hist_r[i] = 0; }
}

// ---------------- fused histogram ---------------------------------------------
__global__ __launch_bounds__(256) void hist3_kernel(
    const int* __restrict__ d0, const int* __restrict__ d1,
    const int* __restrict__ d2, int E0, int E1, int E2)
{
    int et = blockIdx.y;
    const int* dst = (et == 0) ? d0 : (et == 1) ? d1 : d2;
    int* hist = (et == 0) ? g_hist_f : (et == 1) ? g_hist_rb : g_hist_r;
    int E = (et == 0) ? E0 : (et == 1) ? E1 : E2;
    int i = blockIdx.x * blockDim.x + threadIdx.x;
    if (i < E) atomicAdd(&hist[dst[i]], 1);
}

// ---------------- per-etype exclusive scan ------------------------------------
__global__ __launch_bounds__(1024) void scan_kernel(int n)
{
    const int* hist; int* ptr; int* cur;
    if      (blockIdx.x == 0) { hist = g_hist_f;  ptr = g_ptr_f;  cur = g_cur_f;  }
    else if (blockIdx.x == 1) { hist = g_hist_rb; ptr = g_ptr_rb; cur = g_cur_rb; }
    else                      { hist = g_hist_r;  ptr = g_ptr_r;  cur = g_cur_r;  }

    const int T = 1024;
    int chunk = (n + T - 1) / T;
    int lo = threadIdx.x * chunk;
    int hi = lo + chunk; if (hi > n) hi = n;
    if (lo > n) lo = n;

    int s = 0;
    for (int i = lo; i < hi; i++) s += hist[i];

    __shared__ int warpsum[32];
    int lane = threadIdx.x & 31, wid = threadIdx.x >> 5;
    int incl = s;
#pragma unroll
    for (int off = 1; off < 32; off <<= 1) {
        int t = __shfl_up_sync(0xffffffffu, incl, off);
        if (lane >= off) incl += t;
    }
    if (lane == 31) warpsum[wid] = incl;
    __syncthreads();
    if (wid == 0) {
        int w = warpsum[lane];
#pragma unroll
        for (int off = 1; off < 32; off <<= 1) {
            int t = __shfl_up_sync(0xffffffffu, w, off);
            if (lane >= off) w += t;
        }
        warpsum[lane] = w;
    }
    __syncthreads();
    int excl = incl - s + (wid ? warpsum[wid - 1] : 0);
    for (int i = lo; i < hi; i++) {
        ptr[i] = excl; cur[i] = excl; excl += hist[i];
    }
    if (threadIdx.x == 0) ptr[n] = warpsum[31];
}

// ---------------- fused permute -----------------------------------------------
__global__ __launch_bounds__(256) void permute3_kernel(
    const int* __restrict__ s0, const int* __restrict__ d0,
    const int* __restrict__ s1, const int* __restrict__ d1,
    const int* __restrict__ s2, const int* __restrict__ d2,
    int E0, int E1, int E2)
{
    int et = blockIdx.y;
    const int* src = (et == 0) ? s0 : (et == 1) ? s1 : s2;
    const int* dst = (et == 0) ? d0 : (et == 1) ? d1 : d2;
    int* cur = (et == 0) ? g_cur_f : (et == 1) ? g_cur_rb : g_cur_r;
    int* srclist = (et == 0) ? g_srcl_f : (et == 1) ? g_srcl_rb : g_srcl_r;
    int E = (et == 0) ? E0 : (et == 1) ? E1 : E2;
    int i = blockIdx.x * blockDim.x + threadIdx.x;
    if (i < E) {
        int d = dst[i];
        int p = atomicAdd(&cur[d], 1);
        srclist[p] = src[i];
    }
}

// ---------------- fused gather ------------------------------------------------
__global__ __launch_bounds__(256) void gather3_kernel(
    const float4* __restrict__ feat_u, const float4* __restrict__ feat_i)
{
    int et = blockIdx.y;
    const float4* feat = (et == 1) ? feat_i : feat_u;
    const int* ptr = (et == 0) ? g_ptr_f : (et == 1) ? g_ptr_rb : g_ptr_r;
    const int* srclist = (et == 0) ? g_srcl_f : (et == 1) ? g_srcl_rb : g_srcl_r;
    float4* acc = (float4*)((et == 0) ? g_acc_f : (et == 1) ? g_acc_rb : g_acc_r);

    int node = (blockIdx.x * 256 + threadIdx.x) >> 5;
    int lane = threadIdx.x & 31;
    if (node >= NROWS) return;
    int beg = __ldg(&ptr[node]);
    int end = __ldg(&ptr[node + 1]);
    int deg = end - beg;

    float4 s = make_float4(0.f, 0.f, 0.f, 0.f);
    int e = beg;
    for (; e + 8 <= end; e += 8) {
        int si[8];
#pragma unroll
        for (int j = 0; j < 8; j++) si[j] = __ldg(&srclist[e + j]);
        float4 v[8];
#pragma unroll
        for (int j = 0; j < 8; j++) v[j] = feat[(size_t)si[j] * 32 + lane];
#pragma unroll
        for (int j = 0; j < 8; j++) {
            s.x += v[j].x; s.y += v[j].y; s.z += v[j].z; s.w += v[j].w;
        }
    }
    for (; e + 4 <= end; e += 4) {
        int si[4];
#pragma unroll
        for (int j = 0; j < 4; j++) si[j] = __ldg(&srclist[e + j]);
        float4 v[4];
#pragma unroll
        for (int j = 0; j < 4; j++) v[j] = feat[(size_t)si[j] * 32 + lane];
#pragma unroll
        for (int j = 0; j < 4; j++) {
            s.x += v[j].x; s.y += v[j].y; s.z += v[j].z; s.w += v[j].w;
        }
    }
    for (; e < end; e++) {
        float4 v = feat[(size_t)__ldg(&srclist[e]) * 32 + lane];
        s.x += v.x; s.y += v.y; s.z += v.z; s.w += v.w;
    }
    float inv = __fdividef(1.0f, (float)(deg > 0 ? deg : 1));
    s.x *= inv; s.y *= inv; s.z *= inv; s.w *= inv;
    acc[(size_t)node * 32 + lane] = s;
}

// ---------------- packed fp32x2 helpers --------------------------------------
__device__ __forceinline__ u64 ffma2(u64 a, u64 b, u64 c) {
    u64 d;
    asm("fma.rn.f32x2 %0, %1, %2, %3;" : "=l"(d) : "l"(a), "l"(b), "l"(c));
    return d;
}
__device__ __forceinline__ u64 dup2(float x) {
    u64 r;
    asm("mov.b64 %0, {%1, %1};" : "=l"(r) : "f"(x));
    return r;
}
union F2U { u64 u; float2 f; };

// ---------------- GEMM: BM=128, BN=128, BK=16, 256 thr, 8x8 thread tile -------
// blockIdx.y==0: out_user = mean_f @ W_f^T + mean_rb @ W_rb^T + masked biases
// blockIdx.y==1: out_item = mean_r @ W_r^T + masked bias
#define ASTRIDE 132

__global__ __launch_bounds__(256, 2) void gemm_big(
    float* __restrict__ out_user, float* __restrict__ out_item,
    const float* __restrict__ W_f, const float* __restrict__ b_f,
    const float* __restrict__ W_rb, const float* __restrict__ b_rb,
    const float* __restrict__ W_r, const float* __restrict__ b_r)
{
    __shared__ __align__(16) float As[16][ASTRIDE];
    __shared__ __align__(16) float Ws[16][128];

    const int tid = threadIdx.x;
    const int tx = tid & 15;         // 16 col groups: cols tx*4 and 64+tx*4
    const int ty = tid >> 4;         // 16 row groups x 8 rows
    const int row0 = blockIdx.x * 128;
    const bool user = (blockIdx.y == 0);
    const int nkt = user ? 16 : 8;   // k-tiles: (2 segs for user) x (128/BK = 8)
    float* out = user ? out_user : out_item;

    // A-stage mapping: 2 threads per row, 8 k each
    const int a_row = tid >> 1;          // 0..127
    const int a_k   = (tid & 1) * 8;     // 0 or 8
    const int garow = row0 + a_row;
    // W-stage mapping: thread covers col w_n, 8 k
    const int w_n = tid & 127;
    const int w_k = (tid >> 7) * 8;

    u64 C[8][4];
#pragma unroll
    for (int m = 0; m < 8; m++)
#pragma unroll
        for (int c = 0; c < 4; c++) C[m][c] = 0ull;

    for (int kt = 0; kt < nkt; kt++) {
        const int seg = kt >> 3;             // 0 for item (nkt=8)
        const int kc = (kt & 7) * 16;        // 0..112 — full D=128 coverage
        const float* acc = user ? (seg ? g_acc_rb : g_acc_f) : g_acc_r;
        const float* W = user ? (seg ? W_rb : W_f) : W_r;

        float4 a0 = make_float4(0.f, 0.f, 0.f, 0.f), a1 = a0;
        if (garow < NROWS) {
            a0 = *reinterpret_cast<const float4*>(acc + (size_t)garow * D + kc + a_k);
            a1 = *reinterpret_cast<const float4*>(acc + (size_t)garow * D + kc + a_k + 4);
        }
        float4 w0 = *reinterpret_cast<const float4*>(W + (size_t)w_n * D + kc + w_k);
        float4 w1 = *reinterpret_cast<const float4*>(W + (size_t)w_n * D + kc + w_k + 4);

        __syncthreads();
        As[a_k + 0][a_row] = a0.x;
        As[a_k + 1][a_row] = a0.y;
        As[a_k + 2][a_row] = a0.z;
        As[a_k + 3][a_row] = a0.w;
        As[a_k + 4][a_row] = a1.x;
        As[a_k + 5][a_row] = a1.y;
        As[a_k + 6][a_row] = a1.z;
        As[a_k + 7][a_row] = a1.w;
        Ws[w_k + 0][w_n] = w0.x;
        Ws[w_k + 1][w_n] = w0.y;
        Ws[w_k + 2][w_n] = w0.z;
        Ws[w_k + 3][w_n] = w0.w;
        Ws[w_k + 4][w_n] = w1.x;
        Ws[w_k + 5][w_n] = w1.y;
        Ws[w_k + 6][w_n] = w1.z;
        Ws[w_k + 7][w_n] = w1.w;
        __syncthreads();

#pragma unroll
        for (int k = 0; k < 16; k++) {
            float4 ar0 = *reinterpret_cast<const float4*>(&As[k][ty * 8]);
            float4 ar1 = *reinterpret_cast<const float4*>(&As[k][ty * 8 + 4]);
            ulonglong2 wlo = *reinterpret_cast<const ulonglong2*>(&Ws[k][tx * 4]);
            ulonglong2 whi = *reinterpret_cast<const ulonglong2*>(&Ws[k][64 + tx * 4]);
            u64 ad[8];
            ad[0] = dup2(ar0.x); ad[1] = dup2(ar0.y);
            ad[2] = dup2(ar0.z); ad[3] = dup2(ar0.w);
            ad[4] = dup2(ar1.x); ad[5] = dup2(ar1.y);
            ad[6] = dup2(ar1.z); ad[7] = dup2(ar1.w);
#pragma unroll
            for (int m = 0; m < 8; m++) {
                C[m][0] = ffma2(ad[m], wlo.x, C[m][0]);
                C[m][1] = ffma2(ad[m], wlo.y, C[m][1]);
                C[m][2] = ffma2(ad[m], whi.x, C[m][2]);
                C[m][3] = ffma2(ad[m], whi.y, C[m][3]);
            }
        }
    }

    // epilogue
    const float* bias0 = user ? b_f : b_r;
    const int* cnt0 = user ? g_hist_f : g_hist_r;
    float4 blo0 = *reinterpret_cast<const float4*>(bias0 + tx * 4);
    float4 bhi0 = *reinterpret_cast<const float4*>(bias0 + 64 + tx * 4);
    float4 blo1 = make_float4(0.f, 0.f, 0.f, 0.f), bhi1 = blo1;
    if (user) {
        blo1 = *reinterpret_cast<const float4*>(b_rb + tx * 4);
        bhi1 = *reinterpret_cast<const float4*>(b_rb + 64 + tx * 4);
    }
#pragma unroll
    for (int m = 0; m < 8; m++) {
        int r = row0 + ty * 8 + m;
        if (r >= NROWS) continue;
        float m0 = (cnt0[r] > 0) ? 1.0f : 0.0f;
        float m1 = (user && g_hist_rb[r] > 0) ? 1.0f : 0.0f;
        F2U c0, c1, c2, c3;
        c0.u = C[m][0]; c1.u = C[m][1]; c2.u = C[m][2]; c3.u = C[m][3];
        float4 olo, ohi;
        olo.x = c0.f.x + blo0.x * m0 + blo1.x * m1;
        olo.y = c0.f.y + blo0.y * m0 + blo1.y * m1;
        olo.z = c1.f.x + blo0.z * m0 + blo1.z * m1;
        olo.w = c1.f.y + blo0.w * m0 + blo1.w * m1;
        ohi.x = c2.f.x + bhi0.x * m0 + bhi1.x * m1;
        ohi.y = c2.f.y + bhi0.y * m0 + bhi1.y * m1;
        ohi.z = c3.f.x + bhi0.z * m0 + bhi1.z * m1;
        ohi.w = c3.f.y + bhi0.w * m0 + bhi1.w * m1;
        *reinterpret_cast<float4*>(out + (size_t)r * D + tx * 4) = olo;
        *reinterpret_cast<float4*>(out + (size_t)r * D + 64 + tx * 4) = ohi;
    }
}

// ---------------- launch ------------------------------------------------------
extern "C" void kernel_launch(void* const* d_in, const int* in_sizes, int n_in,
                              void* d_out, int out_size)
{
    const float* feat_user = (const float*)d_in[0];
    const float* feat_item = (const float*)d_in[1];
    const float* W_f  = (const float*)d_in[2];
    const float* b_f  = (const float*)d_in[3];
    const float* W_r  = (const float*)d_in[4];
    const float* b_r  = (const float*)d_in[5];
    const float* W_rb = (const float*)d_in[6];
    const float* b_rb = (const float*)d_in[7];
    const int* src_f  = (const int*)d_in[8];
    const int* dst_f  = (const int*)d_in[9];
    const int* src_r  = (const int*)d_in[10];
    const int* dst_r  = (const int*)d_in[11];
    const int* src_rb = (const int*)d_in[12];
    const int* dst_rb = (const int*)d_in[13];
    const int E_f  = in_sizes[8];
    const int E_rb = in_sizes[12];
    const int E_r  = in_sizes[10];

    float* out_user = (float*)d_out;
    float* out_item = (float*)d_out + (size_t)NU * D;

    int Emax = E_f > E_rb ? E_f : E_rb;
    if (E_r > Emax) Emax = E_r;

    zero_hist_kernel<<<(NU + 255) / 256, 256>>>();

    {
        dim3 g((Emax + 255) / 256, 3);
        hist3_kernel<<<g, 256>>>(dst_f, dst_rb, dst_r, E_f, E_rb, E_r);
    }

    scan_kernel<<<3, 1024>>>(NU);

    {
        dim3 g((Emax + 255) / 256, 3);
        permute3_kernel<<<g, 256>>>(src_f, dst_f, src_rb, dst_rb, src_r, dst_r,
                                    E_f, E_rb, E_r);
    }

    {
        dim3 g((NROWS * 32 + 255) / 256, 3);
        gather3_kernel<<<g, 256>>>((const float4*)feat_user,
                                   (const float4*)feat_item);
    }

    {
        dim3 g((NROWS + 127) / 128, 2);
        gemm_big<<<g, 256>>>(out_user, out_item,
                             W_f, b_f, W_rb, b_rb, W_r, b_r);
    }
}